// round 8
// baseline (speedup 1.0000x reference)
#include <cuda_runtime.h>

// TriangleLinear on GB300 (sm_103a) — single fused kernel.
// out[b, 8191-r] = bias[r] + sum_{c >= s(r)} W[wb(r) + c] * x[b, c],  s(r)=max(r-4,0)
// wb(r) = r*8192 - tri(r) - s(r), tri(r) = (r-5)(r-4)/2 for r>=5 else 0.
//
// Stage 1: blocks 0..63 transpose x -> xT[col][b]; gate on g_ready==64.
// Stage 2: warp (q,h): rows 4q..4q+3 + mirrors, column 128-blocks k%4==h.
//          All 4 warps of a block share h (shared xT stream -> L1 hits).
//          Packed fma.rn.f32x2 accumulators; guard blocks peeled.
// Stage 3: per-q last-arriver warp combines the 4 h-partials (+bias, flip)
//          via __ldcg and writes out. Counters self-reset for graph replay.

constexpr int N = 8192;
constexpr int BATCH = 8;
constexpr int HS = 4;
constexpr int NQ = 1024;

__device__ __align__(16) float g_xT[N * BATCH];          // xT[col*8 + b]
__device__ __align__(16) float g_partial[HS][BATCH][N];  // [h][b][flipped col]
__device__ int g_cnt[NQ];
__device__ int g_ready;
__device__ int g_done;

// ---- packed fp32x2 helpers (Blackwell) ----
__device__ __forceinline__ unsigned long long splat2(float v) {
    unsigned long long r;
    asm("mov.b64 %0, {%1, %1};" : "=l"(r) : "f"(v));
    return r;
}
__device__ __forceinline__ void pfma(unsigned long long& d,
                                     unsigned long long a, unsigned long long b) {
    asm("fma.rn.f32x2 %0, %1, %2, %0;" : "+l"(d) : "l"(a), "l"(b));
}
__device__ __forceinline__ float2 unpack2(unsigned long long v) {
    float2 f;
    asm("mov.b64 {%0, %1}, %2;" : "=f"(f.x), "=f"(f.y) : "l"(v));
    return f;
}

// ---------------- main block body ----------------
template<bool GT, bool BOT, bool GB>
__device__ __forceinline__ void do_block(
    int c, int lane, const float* __restrict__ w,
    const int* st, const int* wbT, const int* sb, const int* wbB,
    unsigned long long accT[4][4], unsigned long long accB[4][4])
{
    // front-batch ALL x loads for this 128-col block (8 x LDG.128)
    unsigned long long xv[4][4];
#pragma unroll
    for (int j = 0; j < 4; j++) {
        const int col = c + lane + 32 * j;
        const ulonglong2* xp = (const ulonglong2*)(g_xT + col * BATCH);
        const ulonglong2 lo = __ldg(xp);
        const ulonglong2 hi = __ldg(xp + 1);
        xv[j][0] = lo.x; xv[j][1] = lo.y; xv[j][2] = hi.x; xv[j][3] = hi.y;
    }

#pragma unroll
    for (int j = 0; j < 4; j++) {
        const int col = c + lane + 32 * j;
        float wvT[4], wvB[4];
#pragma unroll
        for (int i = 0; i < 4; i++) {
            wvT[i] = __ldcs(w + wbT[i] + col);
            if (GT) wvT[i] = (col >= st[i]) ? wvT[i] : 0.0f;
        }
        if (BOT) {
#pragma unroll
            for (int i = 0; i < 4; i++) {
                wvB[i] = __ldcs(w + wbB[i] + col);
                if (GB) wvB[i] = (col >= sb[i]) ? wvB[i] : 0.0f;
            }
        }
#pragma unroll
        for (int i = 0; i < 4; i++) {
            const unsigned long long ws = splat2(wvT[i]);
            pfma(accT[i][0], ws, xv[j][0]);
            pfma(accT[i][1], ws, xv[j][1]);
            pfma(accT[i][2], ws, xv[j][2]);
            pfma(accT[i][3], ws, xv[j][3]);
        }
        if (BOT) {
#pragma unroll
            for (int i = 0; i < 4; i++) {
                const unsigned long long ws = splat2(wvB[i]);
                pfma(accB[i][0], ws, xv[j][0]);
                pfma(accB[i][1], ws, xv[j][1]);
                pfma(accB[i][2], ws, xv[j][2]);
                pfma(accB[i][3], ws, xv[j][3]);
            }
        }
    }
}

// ---------------- fused kernel ----------------
__global__ __launch_bounds__(128)
void tri_fused_kernel(const float* __restrict__ x,
                      const float* __restrict__ w,
                      const float* __restrict__ bias,
                      float* __restrict__ out)
{
    __shared__ float s[BATCH][132];     // transpose staging (pad 132: conflict-free)
    const int tid  = threadIdx.x;
    const int lane = tid & 31;
    const int wid  = tid >> 5;
    const int bid  = blockIdx.x;

    // ---- Stage 1: blocks 0..63 transpose their 128-col slice of x ----
    if (bid < 64) {
        const int c0 = bid * 128;
#pragma unroll
        for (int b = 0; b < BATCH; b++)
            s[b][tid] = __ldg(x + b * N + c0 + tid);
        __syncthreads();
#pragma unroll
        for (int kk = 0; kk < 8; kk++) {
            const int j = kk * 128 + tid;          // 0..1023
            g_xT[c0 * BATCH + j] = s[j & 7][j >> 3];
        }
        __threadfence();
        __syncthreads();
        if (tid == 0) atomicAdd(&g_ready, 1);
    }

    // ---- per-warp row setup (q = row group of 4 + mirror group) ----
    const int h = bid & 3;
    const int q = (bid >> 2) * 4 + wid;            // 0..1023

    int st[4], sb[4], wbT[4], wbB[4];
#pragma unroll
    for (int i = 0; i < 4; i++) {
        const int rt = 4 * q + i;
        const int rb = 8188 - 4 * q + i;
        const int s_t = (rt - 4 > 0) ? (rt - 4) : 0;
        const int s_b = rb - 4;                    // rb >= 4096 always
        const int triT = (rt >= 5) ? ((rt - 5) * (rt - 4)) / 2 : 0;
        const int triB = ((rb - 5) * (rb - 4)) / 2;
        st[i] = s_t;  sb[i] = s_b;
        wbT[i] = rt * N - triT - s_t;
        wbB[i] = rb * N - triB - s_b;
    }

    unsigned long long accT[4][4], accB[4][4];
#pragma unroll
    for (int i = 0; i < 4; i++)
#pragma unroll
        for (int kk = 0; kk < 4; kk++) { accT[i][kk] = 0ull; accB[i][kk] = 0ull; }

    // ---- gate: wait for full xT ----
    if (tid == 0) {
        while (*(volatile int*)&g_ready < 64) __nanosleep(128);
    }
    __syncthreads();
    __threadfence();

    // ---- Stage 2: main loop ----
    const int kTopFirst = st[0] >> 7;
    const int kTopLast  = st[3] >> 7;
    const int kBotFirst = sb[0] >> 7;
    const int kBotLast  = sb[3] >> 7;

    int k = kTopFirst + ((h - kTopFirst) & 3);     // first block of residue h

    if (k <= kTopLast && k < kBotFirst) {
        do_block<true, false, false>(k << 7, lane, w, st, wbT, sb, wbB, accT, accB);
        k += 4;
    }
    for (; k < kBotFirst; k += 4)
        do_block<false, false, false>(k << 7, lane, w, st, wbT, sb, wbB, accT, accB);

    if (k < 64 && k <= kBotLast) {
        do_block<true, true, true>(k << 7, lane, w, st, wbT, sb, wbB, accT, accB);
        k += 4;
    }
    for (; k < 64; k += 4)
        do_block<false, true, false>(k << 7, lane, w, st, wbT, sb, wbB, accT, accB);

    // ---- lane-reduce, store partials (pre-flipped) ----
#pragma unroll
    for (int i = 0; i < 4; i++) {
        const int rowT = 4 * q + i;
        const int rowB = 8188 - 4 * q + i;
#pragma unroll
        for (int kk = 0; kk < 4; kk++) {
            float2 t2 = unpack2(accT[i][kk]);
            float2 b2 = unpack2(accB[i][kk]);
            float v0 = t2.x, v1 = t2.y, v2 = b2.x, v3 = b2.y;
#pragma unroll
            for (int m = 16; m >= 1; m >>= 1) {
                v0 += __shfl_xor_sync(0xffffffffu, v0, m);
                v1 += __shfl_xor_sync(0xffffffffu, v1, m);
                v2 += __shfl_xor_sync(0xffffffffu, v2, m);
                v3 += __shfl_xor_sync(0xffffffffu, v3, m);
            }
            if (lane == 0) {
                g_partial[h][2 * kk + 0][N - 1 - rowT] = v0;
                g_partial[h][2 * kk + 1][N - 1 - rowT] = v1;
                g_partial[h][2 * kk + 0][N - 1 - rowB] = v2;
                g_partial[h][2 * kk + 1][N - 1 - rowB] = v3;
            }
        }
    }

    // ---- Stage 3: last-arriver combine for this q ----
    __threadfence();
    int old = 0;
    if (lane == 0) old = atomicAdd(&g_cnt[q], 1);
    old = __shfl_sync(0xffffffffu, old, 0);
    if (old == HS - 1) {
        __threadfence();
#pragma unroll
        for (int t2 = 0; t2 < 2; t2++) {
            const int idx = lane + 32 * t2;        // 0..63
            const int ri  = idx >> 3;              // 0..7 (0-3 top, 4-7 bottom)
            const int b   = idx & 7;
            const int row = (ri < 4) ? (4 * q + ri) : (8188 - 4 * q + (ri - 4));
            const int col = N - 1 - row;
            // __ldcg: L2-coherent (plain L1 load could hit a stale sector
            // cached by a neighboring-q finisher on this SM)
            float v = __ldcg(&g_partial[0][b][col])
                    + __ldcg(&g_partial[1][b][col])
                    + __ldcg(&g_partial[2][b][col])
                    + __ldcg(&g_partial[3][b][col])
                    + __ldg(bias + row);
            out[b * N + col] = v;
        }
        if (lane == 0) {
            g_cnt[q] = 0;                          // reset for next graph replay
            int old2 = atomicAdd(&g_done, 1);
            if (old2 == NQ - 1) { g_done = 0; g_ready = 0; }
        }
    }
}

extern "C" void kernel_launch(void* const* d_in, const int* in_sizes, int n_in,
                              void* d_out, int out_size)
{
    const float* x    = (const float*)d_in[0];   // [8, 8192] fp32
    const float* w    = (const float*)d_in[1];   // packed weights fp32
    const float* bias = (const float*)d_in[2];   // [8192] fp32
    float* out        = (float*)d_out;           // [8, 8192] fp32

    tri_fused_kernel<<<1024, 128>>>(x, w, bias, out);
}

// round 9
// speedup vs baseline: 1.0043x; 1.0043x over previous
#include <cuda_runtime.h>

// TriangleLinear on GB300 (sm_103a) — single fused kernel.
// out[b, 8191-r] = bias[r] + sum_{c >= s(r)} W[wb(r) + c] * x[b, c],  s(r)=max(r-4,0)
// wb(r) = r*8192 - tri(r) - s(r), tri(r) = (r-5)(r-4)/2 for r>=5 else 0.
//
// Stage 1: blocks 0..63 transpose x -> xT[col][b]; gate on g_ready==64.
// Stage 2: warp (q,h): rows 4q..4q+3 + mirrors, column 128-blocks k%4==h.
//          All 4 warps of a block share h (shared xT stream -> L1 hits).
//          Packed fma.rn.f32x2 accumulators; guard blocks peeled.
// Stage 3: per-q last-arriver warp combines the 4 h-partials (+bias, flip)
//          via __ldcg and writes out. Counters self-reset for graph replay.

constexpr int N = 8192;
constexpr int BATCH = 8;
constexpr int HS = 4;
constexpr int NQ = 1024;

__device__ __align__(16) float g_xT[N * BATCH];          // xT[col*8 + b]
__device__ __align__(16) float g_partial[HS][BATCH][N];  // [h][b][flipped col]
__device__ int g_cnt[NQ];
__device__ int g_ready;
__device__ int g_done;

// ---- packed fp32x2 helpers (Blackwell) ----
__device__ __forceinline__ unsigned long long splat2(float v) {
    unsigned long long r;
    asm("mov.b64 %0, {%1, %1};" : "=l"(r) : "f"(v));
    return r;
}
__device__ __forceinline__ void pfma(unsigned long long& d,
                                     unsigned long long a, unsigned long long b) {
    asm("fma.rn.f32x2 %0, %1, %2, %0;" : "+l"(d) : "l"(a), "l"(b));
}
__device__ __forceinline__ float2 unpack2(unsigned long long v) {
    float2 f;
    asm("mov.b64 {%0, %1}, %2;" : "=f"(f.x), "=f"(f.y) : "l"(v));
    return f;
}

// ---------------- main block body ----------------
template<bool GT, bool BOT, bool GB>
__device__ __forceinline__ void do_block(
    int c, int lane, const float* __restrict__ w,
    const int* st, const int* wbT, const int* sb, const int* wbB,
    unsigned long long accT[4][4], unsigned long long accB[4][4])
{
    // front-batch ALL x loads for this 128-col block (8 x LDG.128)
    unsigned long long xv[4][4];
#pragma unroll
    for (int j = 0; j < 4; j++) {
        const int col = c + lane + 32 * j;
        const ulonglong2* xp = (const ulonglong2*)(g_xT + col * BATCH);
        const ulonglong2 lo = __ldg(xp);
        const ulonglong2 hi = __ldg(xp + 1);
        xv[j][0] = lo.x; xv[j][1] = lo.y; xv[j][2] = hi.x; xv[j][3] = hi.y;
    }

#pragma unroll
    for (int j = 0; j < 4; j++) {
        const int col = c + lane + 32 * j;
        float wvT[4], wvB[4];
#pragma unroll
        for (int i = 0; i < 4; i++) {
            wvT[i] = __ldcs(w + wbT[i] + col);
            if (GT) wvT[i] = (col >= st[i]) ? wvT[i] : 0.0f;
        }
        if (BOT) {
#pragma unroll
            for (int i = 0; i < 4; i++) {
                wvB[i] = __ldcs(w + wbB[i] + col);
                if (GB) wvB[i] = (col >= sb[i]) ? wvB[i] : 0.0f;
            }
        }
#pragma unroll
        for (int i = 0; i < 4; i++) {
            const unsigned long long ws = splat2(wvT[i]);
            pfma(accT[i][0], ws, xv[j][0]);
            pfma(accT[i][1], ws, xv[j][1]);
            pfma(accT[i][2], ws, xv[j][2]);
            pfma(accT[i][3], ws, xv[j][3]);
        }
        if (BOT) {
#pragma unroll
            for (int i = 0; i < 4; i++) {
                const unsigned long long ws = splat2(wvB[i]);
                pfma(accB[i][0], ws, xv[j][0]);
                pfma(accB[i][1], ws, xv[j][1]);
                pfma(accB[i][2], ws, xv[j][2]);
                pfma(accB[i][3], ws, xv[j][3]);
            }
        }
    }
}

// ---------------- fused kernel ----------------
__global__ __launch_bounds__(128)
void tri_fused_kernel(const float* __restrict__ x,
                      const float* __restrict__ w,
                      const float* __restrict__ bias,
                      float* __restrict__ out)
{
    __shared__ float s[BATCH][132];     // transpose staging (pad 132: conflict-free)
    const int tid  = threadIdx.x;
    const int lane = tid & 31;
    const int wid  = tid >> 5;
    const int bid  = blockIdx.x;

    // ---- Stage 1: blocks 0..63 transpose their 128-col slice of x ----
    if (bid < 64) {
        const int c0 = bid * 128;
#pragma unroll
        for (int b = 0; b < BATCH; b++)
            s[b][tid] = __ldg(x + b * N + c0 + tid);
        __syncthreads();
#pragma unroll
        for (int kk = 0; kk < 8; kk++) {
            const int j = kk * 128 + tid;          // 0..1023
            g_xT[c0 * BATCH + j] = s[j & 7][j >> 3];
        }
        __threadfence();
        __syncthreads();
        if (tid == 0) atomicAdd(&g_ready, 1);
    }

    // ---- per-warp row setup (q = row group of 4 + mirror group) ----
    const int h = bid & 3;
    const int q = (bid >> 2) * 4 + wid;            // 0..1023

    int st[4], sb[4], wbT[4], wbB[4];
#pragma unroll
    for (int i = 0; i < 4; i++) {
        const int rt = 4 * q + i;
        const int rb = 8188 - 4 * q + i;
        const int s_t = (rt - 4 > 0) ? (rt - 4) : 0;
        const int s_b = rb - 4;                    // rb >= 4096 always
        const int triT = (rt >= 5) ? ((rt - 5) * (rt - 4)) / 2 : 0;
        const int triB = ((rb - 5) * (rb - 4)) / 2;
        st[i] = s_t;  sb[i] = s_b;
        wbT[i] = rt * N - triT - s_t;
        wbB[i] = rb * N - triB - s_b;
    }

    unsigned long long accT[4][4], accB[4][4];
#pragma unroll
    for (int i = 0; i < 4; i++)
#pragma unroll
        for (int kk = 0; kk < 4; kk++) { accT[i][kk] = 0ull; accB[i][kk] = 0ull; }

    // ---- gate: wait for full xT ----
    if (tid == 0) {
        while (*(volatile int*)&g_ready < 64) __nanosleep(128);
    }
    __syncthreads();
    __threadfence();

    // ---- Stage 2: main loop ----
    const int kTopFirst = st[0] >> 7;
    const int kTopLast  = st[3] >> 7;
    const int kBotFirst = sb[0] >> 7;
    const int kBotLast  = sb[3] >> 7;

    int k = kTopFirst + ((h - kTopFirst) & 3);     // first block of residue h

    if (k <= kTopLast && k < kBotFirst) {
        do_block<true, false, false>(k << 7, lane, w, st, wbT, sb, wbB, accT, accB);
        k += 4;
    }
    for (; k < kBotFirst; k += 4)
        do_block<false, false, false>(k << 7, lane, w, st, wbT, sb, wbB, accT, accB);

    if (k < 64 && k <= kBotLast) {
        do_block<true, true, true>(k << 7, lane, w, st, wbT, sb, wbB, accT, accB);
        k += 4;
    }
    for (; k < 64; k += 4)
        do_block<false, true, false>(k << 7, lane, w, st, wbT, sb, wbB, accT, accB);

    // ---- lane-reduce, store partials (pre-flipped) ----
#pragma unroll
    for (int i = 0; i < 4; i++) {
        const int rowT = 4 * q + i;
        const int rowB = 8188 - 4 * q + i;
#pragma unroll
        for (int kk = 0; kk < 4; kk++) {
            float2 t2 = unpack2(accT[i][kk]);
            float2 b2 = unpack2(accB[i][kk]);
            float v0 = t2.x, v1 = t2.y, v2 = b2.x, v3 = b2.y;
#pragma unroll
            for (int m = 16; m >= 1; m >>= 1) {
                v0 += __shfl_xor_sync(0xffffffffu, v0, m);
                v1 += __shfl_xor_sync(0xffffffffu, v1, m);
                v2 += __shfl_xor_sync(0xffffffffu, v2, m);
                v3 += __shfl_xor_sync(0xffffffffu, v3, m);
            }
            if (lane == 0) {
                g_partial[h][2 * kk + 0][N - 1 - rowT] = v0;
                g_partial[h][2 * kk + 1][N - 1 - rowT] = v1;
                g_partial[h][2 * kk + 0][N - 1 - rowB] = v2;
                g_partial[h][2 * kk + 1][N - 1 - rowB] = v3;
            }
        }
    }

    // ---- Stage 3: last-arriver combine for this q ----
    __threadfence();
    int old = 0;
    if (lane == 0) old = atomicAdd(&g_cnt[q], 1);
    old = __shfl_sync(0xffffffffu, old, 0);
    if (old == HS - 1) {
        __threadfence();
#pragma unroll
        for (int t2 = 0; t2 < 2; t2++) {
            const int idx = lane + 32 * t2;        // 0..63
            const int ri  = idx >> 3;              // 0..7 (0-3 top, 4-7 bottom)
            const int b   = idx & 7;
            const int row = (ri < 4) ? (4 * q + ri) : (8188 - 4 * q + (ri - 4));
            const int col = N - 1 - row;
            // __ldcg: L2-coherent (plain L1 load could hit a stale sector
            // cached by a neighboring-q finisher on this SM)
            float v = __ldcg(&g_partial[0][b][col])
                    + __ldcg(&g_partial[1][b][col])
                    + __ldcg(&g_partial[2][b][col])
                    + __ldcg(&g_partial[3][b][col])
                    + __ldg(bias + row);
            out[b * N + col] = v;
        }
        if (lane == 0) {
            g_cnt[q] = 0;                          // reset for next graph replay
            int old2 = atomicAdd(&g_done, 1);
            if (old2 == NQ - 1) { g_done = 0; g_ready = 0; }
        }
    }
}

extern "C" void kernel_launch(void* const* d_in, const int* in_sizes, int n_in,
                              void* d_out, int out_size)
{
    const float* x    = (const float*)d_in[0];   // [8, 8192] fp32
    const float* w    = (const float*)d_in[1];   // packed weights fp32
    const float* bias = (const float*)d_in[2];   // [8192] fp32
    float* out        = (float*)d_out;           // [8, 8192] fp32

    tri_fused_kernel<<<1024, 128>>>(x, w, bias, out);
}

// round 10
// speedup vs baseline: 1.0048x; 1.0005x over previous
#include <cuda_runtime.h>

// TriangleLinear on GB300 (sm_103a) — single fused kernel.
// out[b, 8191-r] = bias[r] + sum_{c >= s(r)} W[wb(r) + c] * x[b, c],  s(r)=max(r-4,0)
// wb(r) = r*8192 - tri(r) - s(r), tri(r) = (r-5)(r-4)/2 for r>=5 else 0.
//
// Stage 1: blocks 0..63 transpose x -> xT[col][b]; gate on g_ready==64.
// Stage 2: warp (q,h): rows 4q..4q+3 + mirrors, column 128-blocks k%4==h.
//          All 4 warps of a block share h (shared xT stream -> L1 hits).
//          Packed fma.rn.f32x2 accumulators; guard blocks peeled.
// Stage 3: per-q last-arriver warp combines the 4 h-partials (+bias, flip)
//          via __ldcg and writes out. Counters self-reset for graph replay.

constexpr int N = 8192;
constexpr int BATCH = 8;
constexpr int HS = 4;
constexpr int NQ = 1024;

__device__ __align__(16) float g_xT[N * BATCH];          // xT[col*8 + b]
__device__ __align__(16) float g_partial[HS][BATCH][N];  // [h][b][flipped col]
__device__ int g_cnt[NQ];
__device__ int g_ready;
__device__ int g_done;

// ---- packed fp32x2 helpers (Blackwell) ----
__device__ __forceinline__ unsigned long long splat2(float v) {
    unsigned long long r;
    asm("mov.b64 %0, {%1, %1};" : "=l"(r) : "f"(v));
    return r;
}
__device__ __forceinline__ void pfma(unsigned long long& d,
                                     unsigned long long a, unsigned long long b) {
    asm("fma.rn.f32x2 %0, %1, %2, %0;" : "+l"(d) : "l"(a), "l"(b));
}
__device__ __forceinline__ float2 unpack2(unsigned long long v) {
    float2 f;
    asm("mov.b64 {%0, %1}, %2;" : "=f"(f.x), "=f"(f.y) : "l"(v));
    return f;
}

// ---------------- main block body ----------------
template<bool GT, bool BOT, bool GB>
__device__ __forceinline__ void do_block(
    int c, int lane, const float* __restrict__ w,
    const int* st, const int* wbT, const int* sb, const int* wbB,
    unsigned long long accT[4][4], unsigned long long accB[4][4])
{
    // front-batch ALL x loads for this 128-col block (8 x LDG.128)
    unsigned long long xv[4][4];
#pragma unroll
    for (int j = 0; j < 4; j++) {
        const int col = c + lane + 32 * j;
        const ulonglong2* xp = (const ulonglong2*)(g_xT + col * BATCH);
        const ulonglong2 lo = __ldg(xp);
        const ulonglong2 hi = __ldg(xp + 1);
        xv[j][0] = lo.x; xv[j][1] = lo.y; xv[j][2] = hi.x; xv[j][3] = hi.y;
    }

#pragma unroll
    for (int j = 0; j < 4; j++) {
        const int col = c + lane + 32 * j;
        float wvT[4], wvB[4];
#pragma unroll
        for (int i = 0; i < 4; i++) {
            wvT[i] = __ldcs(w + wbT[i] + col);
            if (GT) wvT[i] = (col >= st[i]) ? wvT[i] : 0.0f;
        }
        if (BOT) {
#pragma unroll
            for (int i = 0; i < 4; i++) {
                wvB[i] = __ldcs(w + wbB[i] + col);
                if (GB) wvB[i] = (col >= sb[i]) ? wvB[i] : 0.0f;
            }
        }
#pragma unroll
        for (int i = 0; i < 4; i++) {
            const unsigned long long ws = splat2(wvT[i]);
            pfma(accT[i][0], ws, xv[j][0]);
            pfma(accT[i][1], ws, xv[j][1]);
            pfma(accT[i][2], ws, xv[j][2]);
            pfma(accT[i][3], ws, xv[j][3]);
        }
        if (BOT) {
#pragma unroll
            for (int i = 0; i < 4; i++) {
                const unsigned long long ws = splat2(wvB[i]);
                pfma(accB[i][0], ws, xv[j][0]);
                pfma(accB[i][1], ws, xv[j][1]);
                pfma(accB[i][2], ws, xv[j][2]);
                pfma(accB[i][3], ws, xv[j][3]);
            }
        }
    }
}

// ---------------- fused kernel ----------------
__global__ __launch_bounds__(128)
void tri_fused_kernel(const float* __restrict__ x,
                      const float* __restrict__ w,
                      const float* __restrict__ bias,
                      float* __restrict__ out)
{
    __shared__ float s[BATCH][132];     // transpose staging (pad 132: conflict-free)
    const int tid  = threadIdx.x;
    const int lane = tid & 31;
    const int wid  = tid >> 5;
    const int bid  = blockIdx.x;

    // ---- Stage 1: blocks 0..63 transpose their 128-col slice of x ----
    if (bid < 64) {
        const int c0 = bid * 128;
#pragma unroll
        for (int b = 0; b < BATCH; b++)
            s[b][tid] = __ldg(x + b * N + c0 + tid);
        __syncthreads();
#pragma unroll
        for (int kk = 0; kk < 8; kk++) {
            const int j = kk * 128 + tid;          // 0..1023
            g_xT[c0 * BATCH + j] = s[j & 7][j >> 3];
        }
        __threadfence();
        __syncthreads();
        if (tid == 0) atomicAdd(&g_ready, 1);
    }

    // ---- per-warp row setup (q = row group of 4 + mirror group) ----
    const int h = bid & 3;
    const int q = (bid >> 2) * 4 + wid;            // 0..1023

    int st[4], sb[4], wbT[4], wbB[4];
#pragma unroll
    for (int i = 0; i < 4; i++) {
        const int rt = 4 * q + i;
        const int rb = 8188 - 4 * q + i;
        const int s_t = (rt - 4 > 0) ? (rt - 4) : 0;
        const int s_b = rb - 4;                    // rb >= 4096 always
        const int triT = (rt >= 5) ? ((rt - 5) * (rt - 4)) / 2 : 0;
        const int triB = ((rb - 5) * (rb - 4)) / 2;
        st[i] = s_t;  sb[i] = s_b;
        wbT[i] = rt * N - triT - s_t;
        wbB[i] = rb * N - triB - s_b;
    }

    unsigned long long accT[4][4], accB[4][4];
#pragma unroll
    for (int i = 0; i < 4; i++)
#pragma unroll
        for (int kk = 0; kk < 4; kk++) { accT[i][kk] = 0ull; accB[i][kk] = 0ull; }

    // ---- gate: wait for full xT ----
    if (tid == 0) {
        while (*(volatile int*)&g_ready < 64) __nanosleep(128);
    }
    __syncthreads();
    __threadfence();

    // ---- Stage 2: main loop ----
    const int kTopFirst = st[0] >> 7;
    const int kTopLast  = st[3] >> 7;
    const int kBotFirst = sb[0] >> 7;
    const int kBotLast  = sb[3] >> 7;

    int k = kTopFirst + ((h - kTopFirst) & 3);     // first block of residue h

    if (k <= kTopLast && k < kBotFirst) {
        do_block<true, false, false>(k << 7, lane, w, st, wbT, sb, wbB, accT, accB);
        k += 4;
    }
    for (; k < kBotFirst; k += 4)
        do_block<false, false, false>(k << 7, lane, w, st, wbT, sb, wbB, accT, accB);

    if (k < 64 && k <= kBotLast) {
        do_block<true, true, true>(k << 7, lane, w, st, wbT, sb, wbB, accT, accB);
        k += 4;
    }
    for (; k < 64; k += 4)
        do_block<false, true, false>(k << 7, lane, w, st, wbT, sb, wbB, accT, accB);

    // ---- lane-reduce, store partials (pre-flipped) ----
#pragma unroll
    for (int i = 0; i < 4; i++) {
        const int rowT = 4 * q + i;
        const int rowB = 8188 - 4 * q + i;
#pragma unroll
        for (int kk = 0; kk < 4; kk++) {
            float2 t2 = unpack2(accT[i][kk]);
            float2 b2 = unpack2(accB[i][kk]);
            float v0 = t2.x, v1 = t2.y, v2 = b2.x, v3 = b2.y;
#pragma unroll
            for (int m = 16; m >= 1; m >>= 1) {
                v0 += __shfl_xor_sync(0xffffffffu, v0, m);
                v1 += __shfl_xor_sync(0xffffffffu, v1, m);
                v2 += __shfl_xor_sync(0xffffffffu, v2, m);
                v3 += __shfl_xor_sync(0xffffffffu, v3, m);
            }
            if (lane == 0) {
                g_partial[h][2 * kk + 0][N - 1 - rowT] = v0;
                g_partial[h][2 * kk + 1][N - 1 - rowT] = v1;
                g_partial[h][2 * kk + 0][N - 1 - rowB] = v2;
                g_partial[h][2 * kk + 1][N - 1 - rowB] = v3;
            }
        }
    }

    // ---- Stage 3: last-arriver combine for this q ----
    __threadfence();
    int old = 0;
    if (lane == 0) old = atomicAdd(&g_cnt[q], 1);
    old = __shfl_sync(0xffffffffu, old, 0);
    if (old == HS - 1) {
        __threadfence();
#pragma unroll
        for (int t2 = 0; t2 < 2; t2++) {
            const int idx = lane + 32 * t2;        // 0..63
            const int ri  = idx >> 3;              // 0..7 (0-3 top, 4-7 bottom)
            const int b   = idx & 7;
            const int row = (ri < 4) ? (4 * q + ri) : (8188 - 4 * q + (ri - 4));
            const int col = N - 1 - row;
            // __ldcg: L2-coherent (plain L1 load could hit a stale sector
            // cached by a neighboring-q finisher on this SM)
            float v = __ldcg(&g_partial[0][b][col])
                    + __ldcg(&g_partial[1][b][col])
                    + __ldcg(&g_partial[2][b][col])
                    + __ldcg(&g_partial[3][b][col])
                    + __ldg(bias + row);
            out[b * N + col] = v;
        }
        if (lane == 0) {
            g_cnt[q] = 0;                          // reset for next graph replay
            int old2 = atomicAdd(&g_done, 1);
            if (old2 == NQ - 1) { g_done = 0; g_ready = 0; }
        }
    }
}

extern "C" void kernel_launch(void* const* d_in, const int* in_sizes, int n_in,
                              void* d_out, int out_size)
{
    const float* x    = (const float*)d_in[0];   // [8, 8192] fp32
    const float* w    = (const float*)d_in[1];   // packed weights fp32
    const float* bias = (const float*)d_in[2];   // [8192] fp32
    float* out        = (float*)d_out;           // [8, 8192] fp32

    tri_fused_kernel<<<1024, 128>>>(x, w, bias, out);
}